// round 13
// baseline (speedup 1.0000x reference)
#include <cuda_runtime.h>

#define NT 128
#define NH 8
#define NL 3
#define LOG2E 1.4426950408889634f

#define O_WK  0
#define O_WQ  24
#define O_WV  48
#define O_WP  72
#define O_BP  96
#define O_W1  99
#define O_B1  111
#define O_W2  123
#define O_B2  135
#define O_WLM 138
#define O_BLM 139
#define NWTS  140

__device__ __forceinline__ float ex2(float x) {
    float y;
    asm("ex2.approx.ftz.f32 %0, %1;" : "=f"(y) : "f"(x));
    return y;
}

__device__ __forceinline__ float redux_max_nn(float x) {
    unsigned r;
    asm("redux.sync.max.u32 %0, %1, 0xffffffff;" : "=r"(r) : "r"(__float_as_uint(x)));
    return __uint_as_float(r);
}
__device__ __forceinline__ float redux_min_nn(float x) {
    unsigned r;
    asm("redux.sync.min.u32 %0, %1, 0xffffffff;" : "=r"(r) : "r"(__float_as_uint(x)));
    return __uint_as_float(r);
}

struct OS { float m, d, n; };
__device__ __forceinline__ OS comb(OS a, OS b) {
    float mx = fmaxf(a.m, b.m);
    float mn = fminf(a.m, b.m);
    float e  = ex2(mn - mx);
    bool  bl = a.m < b.m;
    float sa = bl ? e : 1.0f;
    float sb = bl ? 1.0f : e;
    OS r; r.m = mx; r.d = fmaf(a.d, sa, b.d * sb); r.n = fmaf(a.n, sa, b.n * sb);
    return r;
}

// full exclusive-prefix online-softmax scan for one (head, batch), monoid version
__device__ __forceinline__ void monoid_scan(
    float ch, float xx0, float xx1, float xx2, float xx3,
    float uu0, float uu1, float uu2, float uu3, int lid,
    float& h0, float& h1, float& h2, float& h3)
{
    OS a0 = { ch*uu0, 1.0f, xx0 };
    OS a1 = comb(a0, { ch*uu1, 1.0f, xx1 });
    OS a2 = comb(a1, { ch*uu2, 1.0f, xx2 });
    OS a3 = comb(a2, { ch*uu3, 1.0f, xx3 });
    OS agg = a3;
    #pragma unroll
    for (int o = 1; o < 32; o <<= 1) {
        OS up;
        up.m = __shfl_up_sync(0xffffffffu, agg.m, o);
        up.d = __shfl_up_sync(0xffffffffu, agg.d, o);
        up.n = __shfl_up_sync(0xffffffffu, agg.n, o);
        if (lid >= o) agg = comb(up, agg);
    }
    OS P;
    P.m = __shfl_up_sync(0xffffffffu, agg.m, 1);
    P.d = __shfl_up_sync(0xffffffffu, agg.d, 1);
    P.n = __shfl_up_sync(0xffffffffu, agg.n, 1);
    if (lid == 0) { P.m = -1e30f; P.d = 0.0f; P.n = 0.0f; }
    OS q1 = comb(P, a0);
    OS q2 = comb(P, a1);
    OS q3 = comb(P, a2);
    h0 = (lid == 0) ? 0.0f : __fdividef(P.n, P.d);
    h1 = __fdividef(q1.n, q1.d);
    h2 = __fdividef(q2.n, q2.d);
    h3 = __fdividef(q3.n, q3.d);
}

__global__ __launch_bounds__(128) void cat_kernel(
    const float* __restrict__ X,
    const float* __restrict__ wk, const float* __restrict__ wq, const float* __restrict__ wv,
    const float* __restrict__ Wp, const float* __restrict__ bp,
    const float* __restrict__ W1, const float* __restrict__ b1,
    const float* __restrict__ W2, const float* __restrict__ b2,
    const float* __restrict__ w_lm, const float* __restrict__ b_lm,
    float* __restrict__ out)
{
    __shared__ float W[NWTS];
    __shared__ float ps[4][2][NT];  // [warp][batch][pos] partial y
    __shared__ float xs[2][NT];     // [batch][pos] x between layers

    const int tid = threadIdx.x;
    const int wr  = tid >> 5;       // 0..3: head pair
    const int lid = tid & 31;
    const int bA  = blockIdx.x * 2;
    const int bB  = bA + 1;

    float4 xvA = reinterpret_cast<const float4*>(X + bA * NT)[lid];
    float4 xvB = reinterpret_cast<const float4*>(X + bB * NT)[lid];

    for (int i = tid; i < NWTS; i += 128) {
        float v;
        if      (i < 24)  v = wk[i];
        else if (i < 48)  v = wq[i - 24];
        else if (i < 72)  v = wv[i - 48];
        else if (i < 96)  v = Wp[i - 72];
        else if (i < 99)  v = bp[i - 96];
        else if (i < 111) v = W1[i - 99];
        else if (i < 123) v = b1[i - 111];
        else if (i < 135) v = W2[i - 123];
        else if (i < 138) v = b2[i - 135];
        else if (i == 138) v = w_lm[0];
        else               v = b_lm[0];
        W[i] = v;
    }
    __syncthreads();

    // hoist only the scan coefficients (FF weights stay in smem to save regs)
    float c_r[NL][2], coef_r[NL][2], camax_r[NL], bp_r[NL], b2_r[NL];
    #pragma unroll
    for (int l = 0; l < NL; ++l) {
        #pragma unroll
        for (int hh = 0; hh < 2; ++hh) {
            const int hg = wr * 2 + hh;
            float cc = W[O_WK + l*NH + hg] * W[O_WQ + l*NH + hg] * LOG2E;
            c_r[l][hh]    = cc;
            coef_r[l][hh] = W[O_WV + l*NH + hg] * W[O_WP + l*NH + hg];
        }
        camax_r[l] = fmaxf(fabsf(c_r[l][0]), fabsf(c_r[l][1]));
        bp_r[l] = W[O_BP + l];
        b2_r[l] = W[O_B2 + l];
    }

    float xA0 = xvA.x, xA1 = xvA.y, xA2 = xvA.z, xA3 = xvA.w;
    float xB0 = xvB.x, xB1 = xvB.y, xB2 = xvB.z, xB3 = xvB.w;

    #pragma unroll
    for (int l = 0; l < NL; ++l) {
        const float uA0 = xA0*xA0, uA1 = xA1*xA1, uA2 = xA2*xA2, uA3 = xA3*xA3;
        const float uB0 = xB0*xB0, uB1 = xB1*xB1, uB2 = xB2*xB2, uB3 = xB3*xB3;

        const float umxA = redux_max_nn(fmaxf(fmaxf(uA0, uA1), fmaxf(uA2, uA3)));
        const float umnA = redux_min_nn(fminf(fminf(uA0, uA1), fminf(uA2, uA3)));
        const float umxB = redux_max_nn(fmaxf(fmaxf(uB0, uB1), fmaxf(uB2, uB3)));
        const float umnB = redux_min_nn(fminf(fminf(uB0, uB1), fminf(uB2, uB3)));

        const float c0 = c_r[l][0], c1 = c_r[l][1];
        const float cf0 = coef_r[l][0], cf1 = coef_r[l][1];
        const float spanm = fmaxf(umxA - umnA, umxB - umnB);

        float pyA0 = 0.f, pyA1 = 0.f, pyA2 = 0.f, pyA3 = 0.f;
        float pyB0 = 0.f, pyB1 = 0.f, pyB2 = 0.f, pyB3 = 0.f;

        if (camax_r[l] * spanm < 120.0f) {
            // ---- 4 streams (2 heads x 2 batches) of additive scans ----
            float e0a[4], n0a[4], d01[4], m01[4], d012[4], m012[4], dT[4], mT[4], sd[4], sn[4];
            const float cc[2] = { c0, c1 };
            #pragma unroll
            for (int hh = 0; hh < 2; ++hh) {
                const float ch = cc[hh];
                {   // batch A -> stream 2*hh
                    const int s = 2*hh;
                    const float K = ((ch > 0.0f) ? ch * umxA : ch * umnA) - 63.0f;
                    float e0 = ex2(fmaf(ch, uA0, -K));
                    float e1 = ex2(fmaf(ch, uA1, -K));
                    float e2 = ex2(fmaf(ch, uA2, -K));
                    float e3 = ex2(fmaf(ch, uA3, -K));
                    float n0 = e0*xA0, n1 = e1*xA1, n2 = e2*xA2, n3 = e3*xA3;
                    float a  = e0 + e1,  b_  = n0 + n1;
                    float a2 = a + e2,   b2_ = b_ + n2;
                    e0a[s]=e0; n0a[s]=n0; d01[s]=a; m01[s]=b_;
                    d012[s]=a2; m012[s]=b2_; dT[s]=a2+e3; mT[s]=b2_+n3;
                    sd[s]=dT[s]; sn[s]=mT[s];
                }
                {   // batch B -> stream 2*hh+1
                    const int s = 2*hh + 1;
                    const float K = ((ch > 0.0f) ? ch * umxB : ch * umnB) - 63.0f;
                    float e0 = ex2(fmaf(ch, uB0, -K));
                    float e1 = ex2(fmaf(ch, uB1, -K));
                    float e2 = ex2(fmaf(ch, uB2, -K));
                    float e3 = ex2(fmaf(ch, uB3, -K));
                    float n0 = e0*xB0, n1 = e1*xB1, n2 = e2*xB2, n3 = e3*xB3;
                    float a  = e0 + e1,  b_  = n0 + n1;
                    float a2 = a + e2,   b2_ = b_ + n2;
                    e0a[s]=e0; n0a[s]=n0; d01[s]=a; m01[s]=b_;
                    d012[s]=a2; m012[s]=b2_; dT[s]=a2+e3; mT[s]=b2_+n3;
                    sd[s]=dT[s]; sn[s]=mT[s];
                }
            }
            #pragma unroll
            for (int o = 1; o < 32; o <<= 1) {
                float ud[4], un[4];
                #pragma unroll
                for (int s = 0; s < 4; ++s) {
                    ud[s] = __shfl_up_sync(0xffffffffu, sd[s], o);
                    un[s] = __shfl_up_sync(0xffffffffu, sn[s], o);
                }
                if (lid >= o) {
                    #pragma unroll
                    for (int s = 0; s < 4; ++s) { sd[s] += ud[s]; sn[s] += un[s]; }
                }
            }
            const float cf[2] = { cf0, cf1 };
            #pragma unroll
            for (int hh = 0; hh < 2; ++hh) {
                {   const int s = 2*hh;
                    float Pd = sd[s] - dT[s], Pn = sn[s] - mT[s];
                    float h0 = __fdividef(Pn, Pd + 1e-37f);
                    float h1 = __fdividef(Pn + n0a[s],  Pd + e0a[s]);
                    float h2 = __fdividef(Pn + m01[s],  Pd + d01[s]);
                    float h3 = __fdividef(Pn + m012[s], Pd + d012[s]);
                    pyA0 = fmaf(h0, cf[hh], pyA0);
                    pyA1 = fmaf(h1, cf[hh], pyA1);
                    pyA2 = fmaf(h2, cf[hh], pyA2);
                    pyA3 = fmaf(h3, cf[hh], pyA3);
                }
                {   const int s = 2*hh + 1;
                    float Pd = sd[s] - dT[s], Pn = sn[s] - mT[s];
                    float h0 = __fdividef(Pn, Pd + 1e-37f);
                    float h1 = __fdividef(Pn + n0a[s],  Pd + e0a[s]);
                    float h2 = __fdividef(Pn + m01[s],  Pd + d01[s]);
                    float h3 = __fdividef(Pn + m012[s], Pd + d012[s]);
                    pyB0 = fmaf(h0, cf[hh], pyB0);
                    pyB1 = fmaf(h1, cf[hh], pyB1);
                    pyB2 = fmaf(h2, cf[hh], pyB2);
                    pyB3 = fmaf(h3, cf[hh], pyB3);
                }
            }
        } else {
            // ---- exact monoid fallback, per head per batch ----
            const float cc[2] = { c0, c1 };
            const float cf[2] = { cf0, cf1 };
            #pragma unroll
            for (int hh = 0; hh < 2; ++hh) {
                float h0, h1, h2, h3;
                monoid_scan(cc[hh], xA0, xA1, xA2, xA3, uA0, uA1, uA2, uA3, lid, h0, h1, h2, h3);
                pyA0 = fmaf(h0, cf[hh], pyA0);
                pyA1 = fmaf(h1, cf[hh], pyA1);
                pyA2 = fmaf(h2, cf[hh], pyA2);
                pyA3 = fmaf(h3, cf[hh], pyA3);
                monoid_scan(cc[hh], xB0, xB1, xB2, xB3, uB0, uB1, uB2, uB3, lid, h0, h1, h2, h3);
                pyB0 = fmaf(h0, cf[hh], pyB0);
                pyB1 = fmaf(h1, cf[hh], pyB1);
                pyB2 = fmaf(h2, cf[hh], pyB2);
                pyB3 = fmaf(h3, cf[hh], pyB3);
            }
        }

        // ---- position-split epilogue over both batches ----
        reinterpret_cast<float4*>(ps[wr][0])[lid] = make_float4(pyA0, pyA1, pyA2, pyA3);
        reinterpret_cast<float4*>(ps[wr][1])[lid] = make_float4(pyB0, pyB1, pyB2, pyB3);
        __syncthreads();

        const int myp = 4 * lid + wr;
        const float bpv = bp_r[l];
        float yA = bpv + ps[0][0][myp] + ps[1][0][myp] + ps[2][0][myp] + ps[3][0][myp];
        float yB = bpv + ps[0][1][myp] + ps[1][1][myp] + ps[2][1][myp] + ps[3][1][myp];

        const float b2v = b2_r[l];
        float fA = b2v, fB = b2v;
        #pragma unroll
        for (int k = 0; k < 4; ++k) {
            const float w1v = W[O_W1 + l*4 + k];
            const float b1v = W[O_B1 + l*4 + k];
            const float w2v = W[O_W2 + l*4 + k];
            fA = fmaf(fmaxf(fmaf(yA, w1v, b1v), 0.0f), w2v, fA);
            fB = fmaf(fmaxf(fmaf(yB, w1v, b1v), 0.0f), w2v, fB);
        }
        xs[0][myp] = yA + fA;
        xs[1][myp] = yB + fB;
        __syncthreads();

        float4 xnA = reinterpret_cast<const float4*>(xs[0])[lid];
        float4 xnB = reinterpret_cast<const float4*>(xs[1])[lid];
        xA0 = xnA.x; xA1 = xnA.y; xA2 = xnA.z; xA3 = xnA.w;
        xB0 = xnB.x; xB1 = xnB.y; xB2 = xnB.z; xB3 = xnB.w;
    }

    const float wlm = W[O_WLM], blm = W[O_BLM];
    if (wr == 0) {
        float4 ov;
        ov.x = fmaf(xA0, wlm, blm);
        ov.y = fmaf(xA1, wlm, blm);
        ov.z = fmaf(xA2, wlm, blm);
        ov.w = fmaf(xA3, wlm, blm);
        reinterpret_cast<float4*>(out + bA * NT)[lid] = ov;
    } else if (wr == 1) {
        float4 ov;
        ov.x = fmaf(xB0, wlm, blm);
        ov.y = fmaf(xB1, wlm, blm);
        ov.z = fmaf(xB2, wlm, blm);
        ov.w = fmaf(xB3, wlm, blm);
        reinterpret_cast<float4*>(out + bB * NT)[lid] = ov;
    }
}

extern "C" void kernel_launch(void* const* d_in, const int* in_sizes, int n_in,
                              void* d_out, int out_size) {
    (void)in_sizes; (void)n_in; (void)out_size;
    cat_kernel<<<256, 128>>>(
        (const float*)d_in[0],  // X
        (const float*)d_in[1],  // wk
        (const float*)d_in[2],  // wq
        (const float*)d_in[3],  // wv
        (const float*)d_in[4],  // Wp
        (const float*)d_in[5],  // bp
        (const float*)d_in[6],  // W1
        (const float*)d_in[7],  // b1
        (const float*)d_in[8],  // W2
        (const float*)d_in[9],  // b2
        (const float*)d_in[10], // w_lm
        (const float*)d_in[11], // b_lm
        (float*)d_out);
}